// round 13
// baseline (speedup 1.0000x reference)
#include <cuda_runtime.h>
#include <cstdint>

#define DC 12                    // internal components
#define NSITE 32768              // 16*16*16*8
#define KMAT 144                 // 12x12
#define DIAGC 4.5f
#define SPB 16                   // sites per tile
#define NTHREADS (SPB * DC)      // 192
#define NBUF 3                   // pipeline depth (buffers)
#define CTAS_PER_SM 4
#define NTILE (NSITE / SPB)      // 2048 tiles
#define STAGE_FLTS (SPB * KMAT)                // 2304 floats per (re|im) plane
#define PLANE_BYTES (STAGE_FLTS * 4)           // 9216 B
#define STAGE_BYTES (PLANE_BYTES * 2)          // 18432 B (re+im)
#define SMEM_BYTES (NBUF * STAGE_BYTES)        // 55296 B -> 4 CTAs/SM (221 KB)

// Dynamic tile queue. Per launch: exactly NTILE successful grabs + gridDim.x
// failed probes, then the last CTA to finish resets both counters to zero —
// so every launch (correctness run + each graph replay) sees identical state.
__device__ unsigned g_tile_ctr = 0;
__device__ unsigned g_done_ctr = 0;

__device__ __forceinline__ uint32_t s2u(const void* p) {
    return (uint32_t)__cvta_generic_to_shared(p);
}

__global__ __launch_bounds__(NTHREADS, CTAS_PER_SM)
void hop_kernel(const float* __restrict__ psi_re, const float* __restrict__ psi_im,
                const float* __restrict__ Kfr,    const float* __restrict__ Kfi,
                const float* __restrict__ Kbr,    const float* __restrict__ Kbi,
                float* __restrict__ out)
{
    extern __shared__ float kbuf[];              // [NBUF][2][STAGE_FLTS]
    __shared__ alignas(8) unsigned long long mbar[NBUF];
    __shared__ unsigned sh_next;

    const int tid = threadIdx.x;
    const unsigned s_loc = (unsigned)tid / DC;
    const unsigned irow  = (unsigned)tid % DC;

    if (tid == 0) {
#pragma unroll
        for (int b = 0; b < NBUF; ++b)
            asm volatile("mbarrier.init.shared.b64 [%0], %1;" :: "r"(s2u(&mbar[b])), "r"(1));
        asm volatile("fence.proxy.async.shared::cta;" ::: "memory");
        sh_next = atomicAdd(&g_tile_ctr, 1u);    // first tile
    }
    __syncthreads();

    // Issue stage st (= 2*mu + dir) of `tile` into buffer `buf`.
    auto issue = [&](int st, unsigned tile, int buf) {
        const unsigned off = (((unsigned)(st >> 1)) * NSITE + tile * SPB) * KMAT;
        const float* srcR = ((st & 1) ? Kbr : Kfr) + off;
        const float* srcI = ((st & 1) ? Kbi : Kfi) + off;
        float* dstR = kbuf + buf * (2 * STAGE_FLTS);
        float* dstI = dstR + STAGE_FLTS;
        const uint32_t mb = s2u(&mbar[buf]);
        asm volatile("mbarrier.arrive.expect_tx.shared.b64 _, [%0], %1;"
                     :: "r"(mb), "r"((unsigned)STAGE_BYTES) : "memory");
        asm volatile("cp.async.bulk.shared::cta.global.mbarrier::complete_tx::bytes "
                     "[%0], [%1], %2, [%3];"
                     :: "r"(s2u(dstR)), "l"(srcR),
                        "r"((unsigned)PLANE_BYTES), "r"(mb) : "memory");
        asm volatile("cp.async.bulk.shared::cta.global.mbarrier::complete_tx::bytes "
                     "[%0], [%1], %2, [%3];"
                     :: "r"(s2u(dstI)), "l"(srcI),
                        "r"((unsigned)PLANE_BYTES), "r"(mb) : "memory");
    };

    unsigned tile = sh_next;          // first tile (grid < NTILE -> always valid)
    unsigned nt_reg = NTILE;          // tid0's copy of the next stolen tile
    unsigned g = 0;                   // continuous stage counter over owned tiles

    // Prologue: fill the 3-deep pipeline with the first tile's stages 0..2.
    if (tid == 0 && tile < NTILE) { issue(0, tile, 0); issue(1, tile, 1); issue(2, tile, 2); }

    while (tile < NTILE) {
        const unsigned s = tile * SPB + s_loc;

        // Lattice coords and neighbor sites for this tile.
        const unsigned x = s & 7, y = (s >> 3) & 15, z = (s >> 7) & 15, t = (s >> 11) & 15;
        unsigned nb[8];   // [fwd_t, bwd_t, fwd_z, bwd_z, fwd_y, bwd_y, fwd_x, bwd_x]
        nb[0] = (s & ~(15u << 11)) | (((t + 1)  & 15) << 11);
        nb[1] = (s & ~(15u << 11)) | (((t + 15) & 15) << 11);
        nb[2] = (s & ~(15u << 7))  | (((z + 1)  & 15) << 7);
        nb[3] = (s & ~(15u << 7))  | (((z + 15) & 15) << 7);
        nb[4] = (s & ~(15u << 3))  | (((y + 1)  & 15) << 3);
        nb[5] = (s & ~(15u << 3))  | (((y + 15) & 15) << 3);
        const unsigned par = (t + z + y) & 1;
        nb[6] = par ? ((s & ~7u) | ((x + 1) & 7)) : s;   // mask_f: r==1
        nb[7] = par ? s : ((s & ~7u) | ((x + 7) & 7));   // mask_b: r==0

        float sr = 0.0f, si = 0.0f;
        unsigned next_tile_loc = NTILE;

#pragma unroll
        for (int st = 0; st < 8; ++st, ++g) {
            const int buf = (int)(g % NBUF);
            const unsigned ph = (g / NBUF) & 1u;

            // Steal the next tile early (latency hidden behind 5 stages).
            if (st == 0 && tid == 0) {
                nt_reg = atomicAdd(&g_tile_ctr, 1u);
                sh_next = nt_reg;
            }

            // Prefetch neighbor psi vector (L1/L2-resident) BEFORE the TMA wait.
            const unsigned v = nb[st] * DC;
            const float4* vr4 = reinterpret_cast<const float4*>(psi_re + v);
            const float4* vi4 = reinterpret_cast<const float4*>(psi_im + v);
            const float4 c0 = vr4[0], c1 = vr4[1], c2 = vr4[2];
            const float4 d0 = vi4[0], d1 = vi4[1], d2 = vi4[2];

            // Wait for this stage's K tile.
            {
                const uint32_t mb = s2u(&mbar[buf]);
                asm volatile(
                    "{\n\t.reg .pred P;\n\t"
                    "W%=:\n\t"
                    "mbarrier.try_wait.parity.shared.b64 P, [%0], %1;\n\t"
                    "@P bra D%=;\n\t"
                    "bra W%=;\n\t"
                    "D%=:\n\t}"
                    :: "r"(mb), "r"(ph) : "memory");
            }

            // Row dot-product from smem: conflict-free LDS.128 (48 B thread stride).
            const float* baseR = kbuf + buf * (2 * STAGE_FLTS) + s_loc * KMAT + irow * DC;
            const float4* kr4 = reinterpret_cast<const float4*>(baseR);
            const float4* ki4 = reinterpret_cast<const float4*>(baseR + STAGE_FLTS);

            {
                float4 a = kr4[0], bb = ki4[0];
                sr = fmaf(a.x, c0.x, sr); sr = fmaf(-bb.x, d0.x, sr);
                si = fmaf(a.x, d0.x, si); si = fmaf( bb.x, c0.x, si);
                sr = fmaf(a.y, c0.y, sr); sr = fmaf(-bb.y, d0.y, sr);
                si = fmaf(a.y, d0.y, si); si = fmaf( bb.y, c0.y, si);
                sr = fmaf(a.z, c0.z, sr); sr = fmaf(-bb.z, d0.z, sr);
                si = fmaf(a.z, d0.z, si); si = fmaf( bb.z, c0.z, si);
                sr = fmaf(a.w, c0.w, sr); sr = fmaf(-bb.w, d0.w, sr);
                si = fmaf(a.w, d0.w, si); si = fmaf( bb.w, c0.w, si);
            }
            {
                float4 a = kr4[1], bb = ki4[1];
                sr = fmaf(a.x, c1.x, sr); sr = fmaf(-bb.x, d1.x, sr);
                si = fmaf(a.x, d1.x, si); si = fmaf( bb.x, c1.x, si);
                sr = fmaf(a.y, c1.y, sr); sr = fmaf(-bb.y, d1.y, sr);
                si = fmaf(a.y, d1.y, si); si = fmaf( bb.y, c1.y, si);
                sr = fmaf(a.z, c1.z, sr); sr = fmaf(-bb.z, d1.z, sr);
                si = fmaf(a.z, d1.z, si); si = fmaf( bb.z, c1.z, si);
                sr = fmaf(a.w, c1.w, sr); sr = fmaf(-bb.w, d1.w, sr);
                si = fmaf(a.w, d1.w, si); si = fmaf( bb.w, c1.w, si);
            }
            {
                float4 a = kr4[2], bb = ki4[2];
                sr = fmaf(a.x, c2.x, sr); sr = fmaf(-bb.x, d2.x, sr);
                si = fmaf(a.x, d2.x, si); si = fmaf( bb.x, c2.x, si);
                sr = fmaf(a.y, c2.y, sr); sr = fmaf(-bb.y, d2.y, sr);
                si = fmaf(a.y, d2.y, si); si = fmaf( bb.y, c2.y, si);
                sr = fmaf(a.z, c2.z, sr); sr = fmaf(-bb.z, d2.z, sr);
                si = fmaf(a.z, d2.z, si); si = fmaf( bb.z, c2.z, si);
                sr = fmaf(a.w, c2.w, sr); sr = fmaf(-bb.w, d2.w, sr);
                si = fmaf(a.w, d2.w, si); si = fmaf( bb.w, c2.w, si);
            }

            // Buffer consumed by all threads -> refill with stage g+NBUF.
            __syncthreads();
            if (st == 0) next_tile_loc = sh_next;   // published by tid0 pre-sync
            if (tid == 0) {
                if (st < 8 - NBUF) {
                    issue(st + NBUF, tile, (int)((g + NBUF) % NBUF));
                } else if (nt_reg < NTILE) {
                    issue(st - (8 - NBUF), nt_reg, (int)((g + NBUF) % NBUF));
                }
            }
        }

        const unsigned o = s * DC + irow;
        out[o]              = fmaf(-0.5f, sr, DIAGC * psi_re[o]);
        out[NSITE * DC + o] = fmaf(-0.5f, si, DIAGC * psi_im[o]);

        tile = next_tile_loc;
    }

    // Last CTA to finish resets the queue for the next (graph-replayed) launch.
    if (tid == 0) {
        __threadfence();
        unsigned d = atomicAdd(&g_done_ctr, 1u);
        if (d == gridDim.x - 1) {
            atomicExch(&g_tile_ctr, 0u);
            atomicExch(&g_done_ctr, 0u);
        }
    }
}

extern "C" void kernel_launch(void* const* d_in, const int* in_sizes, int n_in,
                              void* d_out, int out_size)
{
    const float* psi_re = (const float*)d_in[0];
    const float* psi_im = (const float*)d_in[1];
    const float* Kfr    = (const float*)d_in[2];
    const float* Kfi    = (const float*)d_in[3];
    const float* Kbr    = (const float*)d_in[4];
    const float* Kbi    = (const float*)d_in[5];
    float* out = (float*)d_out;

    // Persistent single wave: 4 CTAs per SM, dynamic tile stealing.
    int dev = 0, nsm = 148;
    cudaGetDevice(&dev);
    cudaDeviceGetAttribute(&nsm, cudaDevAttrMultiProcessorCount, dev);

    cudaFuncSetAttribute(hop_kernel, cudaFuncAttributeMaxDynamicSharedMemorySize,
                         SMEM_BYTES);
    hop_kernel<<<nsm * CTAS_PER_SM, NTHREADS, SMEM_BYTES>>>(
        psi_re, psi_im, Kfr, Kfi, Kbr, Kbi, out);
}

// round 17
// speedup vs baseline: 1.0267x; 1.0267x over previous
#include <cuda_runtime.h>
#include <cstdint>

#define DC 12                    // internal components
#define NSITE 32768              // 16*16*16*8
#define KMAT 144                 // 12x12
#define DIAGC 4.5f
#define SPB 8                    // sites per tile (small granule -> short drain tail)
#define NTHREADS (SPB * DC)      // 96
#define NBUF 3                   // pipeline depth
#define STAGE_FLTS (SPB * KMAT)                // 1152 floats per (re|im) plane
#define PLANE_BYTES (STAGE_FLTS * 4)           // 4608 B
#define STAGE_BYTES (PLANE_BYTES * 2)          // 9216 B (re+im)
#define SMEM_BYTES (NBUF * STAGE_BYTES)        // 27648 B -> 8 CTAs/SM

__device__ __forceinline__ uint32_t s2u(const void* p) {
    return (uint32_t)__cvta_generic_to_shared(p);
}

__global__ __launch_bounds__(NTHREADS)
void hop_kernel(const float* __restrict__ psi_re, const float* __restrict__ psi_im,
                const float* __restrict__ Kfr,    const float* __restrict__ Kfi,
                const float* __restrict__ Kbr,    const float* __restrict__ Kbi,
                float* __restrict__ out)
{
    extern __shared__ float kbuf[];              // [NBUF][2][STAGE_FLTS]
    __shared__ alignas(8) unsigned long long mbar[NBUF];

    const int tid = threadIdx.x;
    const unsigned sbase = blockIdx.x * SPB;
    const unsigned s_loc = (unsigned)tid / DC;
    const unsigned irow  = (unsigned)tid % DC;
    const unsigned s = sbase + s_loc;

    // Lattice coords and neighbor sites.
    const unsigned x = s & 7, y = (s >> 3) & 15, z = (s >> 7) & 15, t = (s >> 11) & 15;
    unsigned nb[8];   // [fwd_t, bwd_t, fwd_z, bwd_z, fwd_y, bwd_y, fwd_x, bwd_x]
    nb[0] = (s & ~(15u << 11)) | (((t + 1)  & 15) << 11);
    nb[1] = (s & ~(15u << 11)) | (((t + 15) & 15) << 11);
    nb[2] = (s & ~(15u << 7))  | (((z + 1)  & 15) << 7);
    nb[3] = (s & ~(15u << 7))  | (((z + 15) & 15) << 7);
    nb[4] = (s & ~(15u << 3))  | (((y + 1)  & 15) << 3);
    nb[5] = (s & ~(15u << 3))  | (((y + 15) & 15) << 3);
    const unsigned par = (t + z + y) & 1;
    nb[6] = par ? ((s & ~7u) | ((x + 1) & 7)) : s;   // mask_f: r==1
    nb[7] = par ? s : ((s & ~7u) | ((x + 7) & 7));   // mask_b: r==0

    if (tid == 0) {
#pragma unroll
        for (int b = 0; b < NBUF; ++b)
            asm volatile("mbarrier.init.shared.b64 [%0], %1;" :: "r"(s2u(&mbar[b])), "r"(1));
        asm volatile("fence.proxy.async.shared::cta;" ::: "memory");
    }
    __syncthreads();

    // Producer: issue stage st = 2*mu + dir into buffer (st % NBUF).
    auto issue = [&](int st) {
        const int b = st % NBUF;
        const unsigned off = (((unsigned)(st >> 1)) * NSITE + sbase) * KMAT;
        const float* srcR = ((st & 1) ? Kbr : Kfr) + off;
        const float* srcI = ((st & 1) ? Kbi : Kfi) + off;
        float* dstR = kbuf + b * (2 * STAGE_FLTS);
        float* dstI = dstR + STAGE_FLTS;
        const uint32_t mb = s2u(&mbar[b]);
        asm volatile("mbarrier.arrive.expect_tx.shared.b64 _, [%0], %1;"
                     :: "r"(mb), "r"((unsigned)STAGE_BYTES) : "memory");
        asm volatile("cp.async.bulk.shared::cta.global.mbarrier::complete_tx::bytes "
                     "[%0], [%1], %2, [%3];"
                     :: "r"(s2u(dstR)), "l"(srcR),
                        "r"((unsigned)PLANE_BYTES), "r"(mb) : "memory");
        asm volatile("cp.async.bulk.shared::cta.global.mbarrier::complete_tx::bytes "
                     "[%0], [%1], %2, [%3];"
                     :: "r"(s2u(dstI)), "l"(srcI),
                        "r"((unsigned)PLANE_BYTES), "r"(mb) : "memory");
    };

    if (tid == 0) { issue(0); issue(1); issue(2); }

    float sr = 0.0f, si = 0.0f;

#pragma unroll
    for (int st = 0; st < 8; ++st) {
        const int b = st % NBUF;
        const unsigned ph = (unsigned)(st / NBUF) & 1;

        // Prefetch neighbor psi vector (L1/L2-resident) BEFORE the TMA wait.
        const unsigned v = nb[st] * DC;
        const float4* vr4 = reinterpret_cast<const float4*>(psi_re + v);
        const float4* vi4 = reinterpret_cast<const float4*>(psi_im + v);
        const float4 c0 = vr4[0], c1 = vr4[1], c2 = vr4[2];
        const float4 d0 = vi4[0], d1 = vi4[1], d2 = vi4[2];

        // Wait for this stage's K tile.
        {
            const uint32_t mb = s2u(&mbar[b]);
            asm volatile(
                "{\n\t.reg .pred P;\n\t"
                "W%=:\n\t"
                "mbarrier.try_wait.parity.shared.b64 P, [%0], %1;\n\t"
                "@P bra D%=;\n\t"
                "bra W%=;\n\t"
                "D%=:\n\t}"
                :: "r"(mb), "r"(ph) : "memory");
        }

        // Row dot-product from smem: conflict-free LDS.128 (48 B thread stride).
        const float* baseR = kbuf + b * (2 * STAGE_FLTS) + s_loc * KMAT + irow * DC;
        const float4* kr4 = reinterpret_cast<const float4*>(baseR);
        const float4* ki4 = reinterpret_cast<const float4*>(baseR + STAGE_FLTS);

        {
            float4 a = kr4[0], bb = ki4[0];
            sr = fmaf(a.x, c0.x, sr); sr = fmaf(-bb.x, d0.x, sr);
            si = fmaf(a.x, d0.x, si); si = fmaf( bb.x, c0.x, si);
            sr = fmaf(a.y, c0.y, sr); sr = fmaf(-bb.y, d0.y, sr);
            si = fmaf(a.y, d0.y, si); si = fmaf( bb.y, c0.y, si);
            sr = fmaf(a.z, c0.z, sr); sr = fmaf(-bb.z, d0.z, sr);
            si = fmaf(a.z, d0.z, si); si = fmaf( bb.z, c0.z, si);
            sr = fmaf(a.w, c0.w, sr); sr = fmaf(-bb.w, d0.w, sr);
            si = fmaf(a.w, d0.w, si); si = fmaf( bb.w, c0.w, si);
        }
        {
            float4 a = kr4[1], bb = ki4[1];
            sr = fmaf(a.x, c1.x, sr); sr = fmaf(-bb.x, d1.x, sr);
            si = fmaf(a.x, d1.x, si); si = fmaf( bb.x, c1.x, si);
            sr = fmaf(a.y, c1.y, sr); sr = fmaf(-bb.y, d1.y, sr);
            si = fmaf(a.y, d1.y, si); si = fmaf( bb.y, c1.y, si);
            sr = fmaf(a.z, c1.z, sr); sr = fmaf(-bb.z, d1.z, sr);
            si = fmaf(a.z, d1.z, si); si = fmaf( bb.z, c1.z, si);
            sr = fmaf(a.w, c1.w, sr); sr = fmaf(-bb.w, d1.w, sr);
            si = fmaf(a.w, d1.w, si); si = fmaf( bb.w, c1.w, si);
        }
        {
            float4 a = kr4[2], bb = ki4[2];
            sr = fmaf(a.x, c2.x, sr); sr = fmaf(-bb.x, d2.x, sr);
            si = fmaf(a.x, d2.x, si); si = fmaf( bb.x, c2.x, si);
            sr = fmaf(a.y, c2.y, sr); sr = fmaf(-bb.y, d2.y, sr);
            si = fmaf(a.y, d2.y, si); si = fmaf( bb.y, c2.y, si);
            sr = fmaf(a.z, c2.z, sr); sr = fmaf(-bb.z, d2.z, sr);
            si = fmaf(a.z, d2.z, si); si = fmaf( bb.z, c2.z, si);
            sr = fmaf(a.w, c2.w, sr); sr = fmaf(-bb.w, d2.w, sr);
            si = fmaf(a.w, d2.w, si); si = fmaf( bb.w, c2.w, si);
        }

        // All threads finished reading buffer b -> safe to refill.
        __syncthreads();
        if (st + NBUF < 8 && tid == 0) issue(st + NBUF);
    }

    const unsigned o = s * DC + irow;
    out[o]              = fmaf(-0.5f, sr, DIAGC * psi_re[o]);
    out[NSITE * DC + o] = fmaf(-0.5f, si, DIAGC * psi_im[o]);
}

extern "C" void kernel_launch(void* const* d_in, const int* in_sizes, int n_in,
                              void* d_out, int out_size)
{
    const float* psi_re = (const float*)d_in[0];
    const float* psi_im = (const float*)d_in[1];
    const float* Kfr    = (const float*)d_in[2];
    const float* Kfi    = (const float*)d_in[3];
    const float* Kbr    = (const float*)d_in[4];
    const float* Kbi    = (const float*)d_in[5];
    float* out = (float*)d_out;

    cudaFuncSetAttribute(hop_kernel, cudaFuncAttributeMaxDynamicSharedMemorySize,
                         SMEM_BYTES);
    hop_kernel<<<NSITE / SPB, NTHREADS, SMEM_BYTES>>>(
        psi_re, psi_im, Kfr, Kfi, Kbr, Kbi, out);
}